// round 13
// baseline (speedup 1.0000x reference)
#include <cuda_runtime.h>
#include <cuda_fp16.h>
#include <math.h>
#include <stdint.h>

// Problem dims
#define Bn   16
#define Ln   1024
#define Dn   256
#define Hn   4
#define DHn  64
#define DFFn 2048
#define Cn   3
#define TOK  (Bn*Ln)          // 16384
#define LDQ  768              // qkv combined row stride

// ---------------- scratch (device globals; no allocations) ----------------
__device__ __half g_x[TOK*Dn];
__device__ __half g_qkv[TOK*LDQ];                 // q|k|v concatenated per token
__device__ __half g_vt[TOK*Dn];                   // V^T per (b,h): [64][1024]
__device__ __half g_ctx[TOK*Dn];
__device__ __half g_t[TOK*DFFn];                  // proj temp + FF hidden
__device__ __half g_f[TOK*Dn];
__device__ __half g_y1[TOK*Dn];
__device__ float  g_y2[TOK*Dn];                   // fp32: drives argmax/segments
__device__ __half g_wqkvT[3*Dn*Dn];               // [768][256]
__device__ float  g_bqkv[3*Dn];
__device__ __half g_woT[Dn*Dn];
__device__ __half g_w1T[Dn*DFFn];
__device__ __half g_w2T[Dn*DFFn];
__device__ int    g_closed[TOK];
__device__ int    g_segstart[TOK];
__device__ int    g_segend[TOK];
__device__ int    g_nseg[Bn];
__device__ float  g_compsum[Bn];
__device__ float  g_kl[1];

// ---------------- helpers ----------------
__device__ __forceinline__ void mma_f16(float d[4],
                                        uint32_t a0, uint32_t a1, uint32_t a2, uint32_t a3,
                                        uint32_t b0, uint32_t b1) {
    asm volatile(
        "mma.sync.aligned.m16n8k16.row.col.f32.f16.f16.f32 "
        "{%0,%1,%2,%3}, {%4,%5,%6,%7}, {%8,%9}, {%0,%1,%2,%3};"
        : "+f"(d[0]), "+f"(d[1]), "+f"(d[2]), "+f"(d[3])
        : "r"(a0), "r"(a1), "r"(a2), "r"(a3), "r"(b0), "r"(b1));
}

__device__ __forceinline__ void cp16(void* smem_dst, const void* gsrc) {
    uint32_t d = (uint32_t)__cvta_generic_to_shared(smem_dst);
    asm volatile("cp.async.cg.shared.global [%0], [%1], 16;" :: "r"(d), "l"(gsrc));
}
#define CP_COMMIT() asm volatile("cp.async.commit_group;" ::: "memory")
#define CP_WAIT(n)  asm volatile("cp.async.wait_group %0;" :: "n"(n) : "memory")

// ======================= HMMA FP16 GEMM (3-stage cp.async pipeline) ================
// C[128,BN](half) = alpha * A[M,K](half) @ Bt[N,K]^T(half) (+bias fp32)(+relu)(+resid half)
// K chunks of 64 halfs (128B/row), 4 k-steps of 16. SMEM word layout identical to the
// proven tf32 kernel: rows of 32 uint32 words, group-swizzle g^=(r&7).
template<int BN>
__global__ __launch_bounds__(256, 2)
void k_mma(const __half* __restrict__ A, int lda,
           const __half* __restrict__ Bt, int ldb,
           __half* __restrict__ Cm, int ldc,
           int K, const float* __restrict__ bias, int relu, float alpha,
           const __half* __restrict__ resid)
{
    constexpr int WARPS_M = (BN == 128) ? 2 : 4;
    constexpr int WARPS_N = 8 / WARPS_M;
    constexpr int WM = 128 / WARPS_M;
    constexpr int WN = BN / WARPS_N;
    constexpr int MT = WM / 16;
    constexpr int NT = WN / 8;
    constexpr int BLOADS = BN / 32;

    extern __shared__ uint32_t smw[];
    uint32_t* As = smw;                       // [3][128*32] words
    uint32_t* Bs = smw + 3 * 128 * 32;        // [3][BN*32] words

    int tid = threadIdx.x;
    int row0 = blockIdx.y * 128;
    int col0 = blockIdx.x * BN;

    int w = tid >> 5, lane = tid & 31;
    int wm = w % WARPS_M, wn = w / WARPS_M;
    int lr = lane >> 2, lc = lane & 3;

    float acc[MT][NT][4];
    #pragma unroll
    for (int i = 0; i < MT; i++)
        #pragma unroll
        for (int j = 0; j < NT; j++)
            #pragma unroll
            for (int t = 0; t < 4; t++) acc[i][j][t] = 0.f;

    const int NC = K >> 6;   // chunks of 64 halfs

    auto issue = [&](int c, int buf) {
        int k0 = c << 6;
        #pragma unroll
        for (int i = 0; i < 4; i++) {
            int idx = tid + 256 * i;
            int r = idx >> 3, g = idx & 7;
            int gs = g ^ (r & 7);
            cp16(As + buf*128*32 + r*32 + gs*4,
                 &A[(size_t)(row0 + r) * lda + k0 + g*8]);
        }
        #pragma unroll
        for (int i = 0; i < BLOADS; i++) {
            int idx = tid + 256 * i;
            int r = idx >> 3, g = idx & 7;
            int gs = g ^ (r & 7);
            cp16(Bs + buf*BN*32 + r*32 + gs*4,
                 &Bt[(size_t)(col0 + r) * ldb + k0 + g*8]);
        }
    };

    issue(0, 0); CP_COMMIT();
    if (NC > 1) { issue(1, 1); CP_COMMIT(); }

    for (int c = 0; c < NC; c++) {
        if (c + 1 < NC) CP_WAIT(1); else CP_WAIT(0);
        __syncthreads();
        if (c + 2 < NC) { issue(c + 2, (c + 2) % 3); CP_COMMIT(); }

        int buf = c % 3;
        const uint32_t* Au = As + buf * 128 * 32;
        const uint32_t* Bu = Bs + buf * BN * 32;
        #pragma unroll
        for (int ks = 0; ks < 4; ks++) {
            uint32_t af[MT][4];
            #pragma unroll
            for (int mt = 0; mt < MT; mt++) {
                int arow = wm * WM + mt * 16 + lr;
                int sw = (arow & 7);
                const uint32_t* base = Au + arow * 32;
                af[mt][0] = base[(((2*ks)   ^ sw) << 2) + lc];
                af[mt][2] = base[(((2*ks+1) ^ sw) << 2) + lc];
                const uint32_t* base8 = Au + (arow + 8) * 32;
                af[mt][1] = base8[(((2*ks)   ^ sw) << 2) + lc];
                af[mt][3] = base8[(((2*ks+1) ^ sw) << 2) + lc];
            }
            uint32_t bf[NT][2];
            #pragma unroll
            for (int nt = 0; nt < NT; nt++) {
                int brow = wn * WN + nt * 8 + lr;
                int sw = (brow & 7);
                const uint32_t* base = Bu + brow * 32;
                bf[nt][0] = base[(((2*ks)   ^ sw) << 2) + lc];
                bf[nt][1] = base[(((2*ks+1) ^ sw) << 2) + lc];
            }
            #pragma unroll
            for (int mt = 0; mt < MT; mt++)
                #pragma unroll
                for (int nt = 0; nt < NT; nt++)
                    mma_f16(acc[mt][nt], af[mt][0], af[mt][1], af[mt][2], af[mt][3],
                            bf[nt][0], bf[nt][1]);
        }
    }

    #pragma unroll
    for (int mt = 0; mt < MT; mt++) {
        int row = row0 + wm * WM + mt * 16 + lr;
        #pragma unroll
        for (int nt = 0; nt < NT; nt++) {
            int col = col0 + wn * WN + nt * 8 + 2 * lc;
            float v0 = acc[mt][nt][0] * alpha, v1 = acc[mt][nt][1] * alpha;
            float v2 = acc[mt][nt][2] * alpha, v3 = acc[mt][nt][3] * alpha;
            if (bias) {
                float b0 = bias[col], b1 = bias[col + 1];
                v0 += b0; v1 += b1; v2 += b0; v3 += b1;
            }
            if (resid) {
                float2 r0 = __half22float2(*(const __half2*)&resid[(size_t)row * ldc + col]);
                float2 r1 = __half22float2(*(const __half2*)&resid[(size_t)(row + 8) * ldc + col]);
                v0 += r0.x; v1 += r0.y; v2 += r1.x; v3 += r1.y;
            }
            if (relu) {
                v0 = fmaxf(v0, 0.f); v1 = fmaxf(v1, 0.f);
                v2 = fmaxf(v2, 0.f); v3 = fmaxf(v3, 0.f);
            }
            *(__half2*)&Cm[(size_t)row * ldc + col] = __floats2half2_rn(v0, v1);
            *(__half2*)&Cm[(size_t)(row + 8) * ldc + col] = __floats2half2_rn(v2, v3);
        }
    }
}

// ======================= fused flash attention (fp16 operands) =====================
// One CTA per (128-query tile, b*4+h). 8 warps, warp = 16 query rows.
// SMEM (uint32 words): Qs 128*32, Ks 2x128*32, Vs 2x64*64, Ps 128*64 = 112 KB.
__global__ __launch_bounds__(256, 1)
void k_flash(const __half* __restrict__ QKV, const __half* __restrict__ Vt,
             __half* __restrict__ O)
{
    extern __shared__ uint32_t us[];
    uint32_t* Qs = us;                   // 128 rows x 32 words
    uint32_t* Ks = us + 4096;            // 2 x 128 x 32
    uint32_t* Vs = us + 12288;           // 2 x 64 x 64
    uint32_t* Ps = us + 20480;           // 128 x 64

    int z = blockIdx.y;
    const __half* q  = QKV + (size_t)(z>>2)*Ln*LDQ + (size_t)(z&3)*DHn;
    const __half* kp = q + 256;
    const __half* vt = Vt + (size_t)z*DHn*Ln;
    __half* o        = O  + (size_t)(z>>2)*Ln*Dn + (size_t)(z&3)*DHn;

    int row0 = blockIdx.x * 128;
    int tid = threadIdx.x, w = tid >> 5, lane = tid & 31;
    int lr = lane >> 2, lc = lane & 3;

    auto issueK = [&](int j, int buf) {
        #pragma unroll
        for (int i = 0; i < 4; i++) {
            int idx = tid + 256*i;
            int r = idx >> 3, g = idx & 7;
            cp16(Ks + buf*4096 + r*32 + ((g ^ (r & 7)) << 2),
                 &kp[(size_t)(j*128 + r)*LDQ + g*8]);
        }
    };
    auto issueV = [&](int j, int buf) {
        #pragma unroll
        for (int i = 0; i < 4; i++) {
            int idx = tid + 256*i;
            int r = idx >> 4, g = idx & 15;
            cp16(Vs + buf*4096 + r*64 + ((g ^ (r & 7)) << 2),
                 &vt[(size_t)r*Ln + j*128 + g*8]);
        }
    };

    #pragma unroll
    for (int i = 0; i < 4; i++) {
        int idx = tid + 256*i;
        int r = idx >> 3, g = idx & 7;
        cp16(Qs + r*32 + ((g ^ (r & 7)) << 2),
             &q[(size_t)(row0 + r)*LDQ + g*8]);
    }
    issueK(0, 0); issueV(0, 0);
    CP_COMMIT();

    float m0 = -1e30f, m1 = -1e30f, l0 = 0.f, l1 = 0.f;
    float oa[8][4];
    #pragma unroll
    for (int n = 0; n < 8; n++)
        #pragma unroll
        for (int t = 0; t < 4; t++) oa[n][t] = 0.f;

    int arow = w*16 + lr;
    int asw = arow & 7;

    for (int j = 0; j < 8; j++) {
        if (j + 1 < 8) {
            issueK(j + 1, (j + 1) & 1); issueV(j + 1, (j + 1) & 1);
            CP_COMMIT();
            CP_WAIT(1);
        } else {
            CP_WAIT(0);
        }
        __syncthreads();

        const uint32_t* Kb = Ks + (j & 1)*4096;
        const uint32_t* Vb = Vs + (j & 1)*4096;

        // ---- S = Q @ K^T  (k = 64 halfs -> 4 k-steps of 16) ----
        float sacc[16][4];
        #pragma unroll
        for (int n = 0; n < 16; n++)
            #pragma unroll
            for (int t = 0; t < 4; t++) sacc[n][t] = 0.f;

        #pragma unroll
        for (int ks = 0; ks < 4; ks++) {
            const uint32_t* ab  = Qs + arow*32;
            const uint32_t* ab8 = Qs + (arow + 8)*32;
            uint32_t a0 = ab [(((2*ks)   ^ asw) << 2) + lc];
            uint32_t a2 = ab [(((2*ks+1) ^ asw) << 2) + lc];
            uint32_t a1 = ab8[(((2*ks)   ^ asw) << 2) + lc];
            uint32_t a3 = ab8[(((2*ks+1) ^ asw) << 2) + lc];
            #pragma unroll
            for (int nt = 0; nt < 16; nt++) {
                int brow = nt*8 + lr;
                int bsw = brow & 7;
                const uint32_t* bb = Kb + brow*32;
                uint32_t b0 = bb[(((2*ks)   ^ bsw) << 2) + lc];
                uint32_t b1 = bb[(((2*ks+1) ^ bsw) << 2) + lc];
                mma_f16(sacc[nt], a0, a1, a2, a3, b0, b1);
            }
        }

        // ---- online softmax ----
        float rm0 = -1e30f, rm1 = -1e30f;
        #pragma unroll
        for (int nt = 0; nt < 16; nt++) {
            #pragma unroll
            for (int t = 0; t < 4; t++) sacc[nt][t] *= 0.125f;
            rm0 = fmaxf(rm0, fmaxf(sacc[nt][0], sacc[nt][1]));
            rm1 = fmaxf(rm1, fmaxf(sacc[nt][2], sacc[nt][3]));
        }
        rm0 = fmaxf(rm0, __shfl_xor_sync(0xffffffff, rm0, 1));
        rm0 = fmaxf(rm0, __shfl_xor_sync(0xffffffff, rm0, 2));
        rm1 = fmaxf(rm1, __shfl_xor_sync(0xffffffff, rm1, 1));
        rm1 = fmaxf(rm1, __shfl_xor_sync(0xffffffff, rm1, 2));
        float mn0 = fmaxf(m0, rm0), mn1 = fmaxf(m1, rm1);
        float sc0 = expf(m0 - mn0), sc1 = expf(m1 - mn1);

        float rs0 = 0.f, rs1 = 0.f;
        #pragma unroll
        for (int nt = 0; nt < 16; nt++) {
            float p0 = expf(sacc[nt][0] - mn0);
            float p1 = expf(sacc[nt][1] - mn0);
            float p2 = expf(sacc[nt][2] - mn1);
            float p3 = expf(sacc[nt][3] - mn1);
            rs0 += p0 + p1; rs1 += p2 + p3;
            // P store: col pair (nt*8+2lc, +1) -> word nt*4+lc -> group nt, word lc
            *(__half2*)(Ps + arow*64 + ((nt ^ asw) << 2) + lc) = __floats2half2_rn(p0, p1);
            *(__half2*)(Ps + (arow + 8)*64 + ((nt ^ asw) << 2) + lc) = __floats2half2_rn(p2, p3);
        }
        rs0 += __shfl_xor_sync(0xffffffff, rs0, 1);
        rs0 += __shfl_xor_sync(0xffffffff, rs0, 2);
        rs1 += __shfl_xor_sync(0xffffffff, rs1, 1);
        rs1 += __shfl_xor_sync(0xffffffff, rs1, 2);
        l0 = l0*sc0 + rs0; l1 = l1*sc1 + rs1;
        m0 = mn0; m1 = mn1;
        #pragma unroll
        for (int nt = 0; nt < 8; nt++) {
            oa[nt][0] *= sc0; oa[nt][1] *= sc0;
            oa[nt][2] *= sc1; oa[nt][3] *= sc1;
        }
        __syncwarp();

        // ---- O += P @ V^T  (k = 128 halfs -> 8 k-steps of 16) ----
        #pragma unroll
        for (int ks = 0; ks < 8; ks++) {
            const uint32_t* ab  = Ps + arow*64;
            const uint32_t* ab8 = Ps + (arow + 8)*64;
            uint32_t a0 = ab [(((2*ks)   ^ asw) << 2) + lc];
            uint32_t a2 = ab [(((2*ks+1) ^ asw) << 2) + lc];
            uint32_t a1 = ab8[(((2*ks)   ^ asw) << 2) + lc];
            uint32_t a3 = ab8[(((2*ks+1) ^ asw) << 2) + lc];
            #pragma unroll
            for (int nt = 0; nt < 8; nt++) {
                int brow = nt*8 + lr;
                int bsw = brow & 7;
                const uint32_t* bb = Vb + brow*64;
                uint32_t b0 = bb[(((2*ks)   ^ bsw) << 2) + lc];
                uint32_t b1 = bb[(((2*ks+1) ^ bsw) << 2) + lc];
                mma_f16(oa[nt], a0, a1, a2, a3, b0, b1);
            }
        }
        __syncthreads();
    }

    float il0 = 1.f / l0, il1 = 1.f / l1;
    int row = row0 + w*16 + lr;
    #pragma unroll
    for (int nt = 0; nt < 8; nt++) {
        int col = nt*8 + 2*lc;
        *(__half2*)&o[(size_t)row*Dn + col] =
            __floats2half2_rn(oa[nt][0]*il0, oa[nt][1]*il0);
        *(__half2*)&o[(size_t)(row + 8)*Dn + col] =
            __floats2half2_rn(oa[nt][2]*il1, oa[nt][3]*il1);
    }
}

// ======================= transposes =======================
__global__ void k_transpose_f2h(const float* __restrict__ in, int ldin,
                                __half* __restrict__ out, int ldout)
{
    __shared__ float tile[32][33];
    int c0 = blockIdx.x*32, r0 = blockIdx.y*32;
    int tx = threadIdx.x, ty = threadIdx.y;   // 32 x 8
    #pragma unroll
    for (int i = 0; i < 32; i += 8)
        tile[ty+i][tx] = in[(size_t)(r0+ty+i)*ldin + c0+tx];
    __syncthreads();
    #pragma unroll
    for (int i = 0; i < 32; i += 8)
        out[(size_t)(c0+ty+i)*ldout + r0+tx] = __float2half(tile[tx][ty+i]);
}

// half->half transpose with per-z offsets (for V^T): off = z*iS1 + (z>>2)*iS2 + (z&3)*iS3
__global__ void k_transpose_h(const __half* __restrict__ in, int ldin,
                              long iS1, long iS2, long iS3,
                              __half* __restrict__ out, int ldout, long oS1)
{
    __shared__ __half tile[32][34];
    int z = blockIdx.z;
    in  += (long)z*iS1 + (long)(z>>2)*iS2 + (long)(z&3)*iS3;
    out += (long)z*oS1;
    int c0 = blockIdx.x*32, r0 = blockIdx.y*32;
    int tx = threadIdx.x, ty = threadIdx.y;   // 32 x 8
    #pragma unroll
    for (int i = 0; i < 32; i += 8)
        tile[ty+i][tx] = in[(size_t)(r0+ty+i)*ldin + c0+tx];
    __syncthreads();
    #pragma unroll
    for (int i = 0; i < 32; i += 8)
        out[(size_t)(c0+ty+i)*ldout + r0+tx] = tile[tx][ty+i];
}

// ---------------- init / bias concat ----------------
__global__ void k_init(float* compsum, float* kl) {
    int t = threadIdx.x;
    if (t < Bn) compsum[t] = 0.f;
    if (t == 0) kl[0] = 0.f;
}
__global__ void k_bcat(const float* bq, const float* bk, const float* bv, float* o) {
    int t = threadIdx.x;
    o[t] = bq[t]; o[256 + t] = bk[t]; o[512 + t] = bv[t];
}

// ---------------- embedding (half out) ----------------
__global__ void k_embed(const int* __restrict__ sidx, const int* __restrict__ cidx,
                        const float* __restrict__ semb, const float* __restrict__ cemb,
                        __half* __restrict__ x) {
    int tok = blockIdx.x;
    int d = threadIdx.x;
    int si = sidx[tok], ci = cidx[tok];
    x[(size_t)tok*Dn + d] = __float2half(semb[si*Dn + d] + cemb[ci*Dn + d]);
}

// ---------------- LayerNorm (half in; half and/or float out) ----------------
__global__ void k_ln(const __half* __restrict__ T,
                     const float* __restrict__ g, const float* __restrict__ b,
                     __half* __restrict__ Yh, float* __restrict__ Yf) {
    int row = blockIdx.x, d = threadIdx.x;
    __shared__ float red[256];
    float v = __half2float(T[(size_t)row*Dn + d]);
    red[d] = v; __syncthreads();
    for (int o = 128; o > 0; o >>= 1) { if (d < o) red[d] += red[d+o]; __syncthreads(); }
    float m = red[0] * (1.f / Dn); __syncthreads();
    float dv = v - m;
    red[d] = dv * dv; __syncthreads();
    for (int o = 128; o > 0; o >>= 1) { if (d < o) red[d] += red[d+o]; __syncthreads(); }
    float var = red[0] * (1.f / Dn);
    float y = dv * rsqrtf(var + 1e-5f) * g[d] + b[d];
    if (Yh) Yh[(size_t)row*Dn + d] = __float2half(y);
    if (Yf) Yf[(size_t)row*Dn + d] = y;
}

// ---------------- logits + KL + boundary (fp32 y2) ----------------
__global__ void k_logits(const float* __restrict__ Y, const float* __restrict__ Wl,
                         const float* __restrict__ bl, int* __restrict__ closed,
                         float* __restrict__ klacc) {
    int warp = (blockIdx.x * blockDim.x + threadIdx.x) >> 5;
    int lane = threadIdx.x & 31;
    if (warp >= TOK) return;
    const float* y = Y + (size_t)warp * Dn;
    float l0 = 0.f, l1 = 0.f, l2 = 0.f;
    #pragma unroll
    for (int i = 0; i < 8; i++) {
        int d = lane + i * 32;
        float yv = y[d];
        l0 += yv * Wl[d*3 + 0];
        l1 += yv * Wl[d*3 + 1];
        l2 += yv * Wl[d*3 + 2];
    }
    #pragma unroll
    for (int o = 16; o > 0; o >>= 1) {
        l0 += __shfl_xor_sync(0xffffffff, l0, o);
        l1 += __shfl_xor_sync(0xffffffff, l1, o);
        l2 += __shfl_xor_sync(0xffffffff, l2, o);
    }
    if (lane == 0) {
        l0 += bl[0]; l1 += bl[1]; l2 += bl[2];
        float mx = fmaxf(l0, fmaxf(l1, l2));
        float lse = logf(expf(l0-mx) + expf(l1-mx) + expf(l2-mx)) + mx;
        float sumlogp = (l0 + l1 + l2) - 3.f * lse;
        atomicAdd(klacc, sumlogp);
        int l = warp & (Ln - 1);
        int boundary = (l0 >= l1 && l0 >= l2) ? 1 : 0;
        closed[warp] = (boundary && l > 0) ? 1 : 0;
    }
}

// ---------------- per-batch serial segment scan ----------------
__global__ void k_segscan(const int* __restrict__ closed, int* __restrict__ sstart,
                          int* __restrict__ send, int* __restrict__ nseg) {
    int b = threadIdx.x;
    if (b >= Bn) return;
    int cnt = 0, start = 0;
    for (int l = 0; l < Ln; l++) {
        if (closed[b*Ln + l]) {
            sstart[b*Ln + cnt] = start;
            send[b*Ln + cnt] = l;
            cnt++; start = l + 1;
        }
    }
    if (start <= Ln - 1) {
        sstart[b*Ln + cnt] = start;
        send[b*Ln + cnt] = Ln - 1;
        cnt++;
    }
    nseg[b] = cnt;
}

// ---------------- segment mean + predicate net, 8 segments per block ----------------
__global__ void k_segpred8(const float* __restrict__ Y, const float* __restrict__ Wp1,
                           const float* __restrict__ bp1, const float* __restrict__ Wp2,
                           const float* __restrict__ bp2, const float* __restrict__ wc,
                           const float* __restrict__ bc,
                           const int* __restrict__ sstart, const int* __restrict__ send,
                           const int* __restrict__ nseg, float* __restrict__ compsum) {
    int b = blockIdx.y;
    int ns = nseg[b];
    int s0 = blockIdx.x * 8;
    if (s0 >= ns) return;
    int cnt = min(8, ns - s0);
    int d = threadIdx.x;
    __shared__ float mean[8][256];
    for (int s = 0; s < cnt; s++) {
        int st = sstart[b*Ln + s0 + s], en = send[b*Ln + s0 + s];
        float sum = 0.f;
        for (int l = st; l <= en; l++)
            sum += Y[((size_t)(b*Ln + l)) * Dn + d];
        mean[s][d] = sum / (float)(en - st + 1);
    }
    for (int s = cnt; s < 8; s++) mean[s][d] = 0.f;
    __syncthreads();

    float acc[8];
    float bp = bp1[d];
    #pragma unroll
    for (int s = 0; s < 8; s++) acc[s] = bp;
    for (int k = 0; k < Dn; k++) {
        float w = Wp1[k*Dn + d];
        #pragma unroll
        for (int s = 0; s < 8; s++) acc[s] += mean[s][k] * w;
    }

    float w2 = Wp2[d];
    __shared__ float red[256];
    __shared__ float comp_total;
    if (d == 0) comp_total = 0.f;
    __syncthreads();
    for (int s = 0; s < cnt; s++) {
        red[d] = fmaxf(acc[s], 0.f) * w2;
        __syncthreads();
        for (int o = 128; o > 0; o >>= 1) { if (d < o) red[d] += red[d+o]; __syncthreads(); }
        if (d == 0) {
            float pin = red[0] + bp2[0];
            float sig = 1.f / (1.f + expf(-pin));
            comp_total += sig * wc[0] + bc[0];
        }
        __syncthreads();
    }
    if (d == 0) atomicAdd(&compsum[b], comp_total);
}

// ---------------- final outputs ----------------
__global__ void k_final(const float* __restrict__ compsum, const int* __restrict__ nseg,
                        const float* __restrict__ kl, float* __restrict__ out) {
    int t = threadIdx.x;
    if (t < Bn) {
        float mc = compsum[t] / (float)nseg[t];
        out[t] = 1.f / (1.f + expf(-mc));
    }
    if (t == Bn) {
        out[Bn] = ((float)TOK * logf(1.f/3.f) - (1.f/3.f) * kl[0]) / (float)Bn;
    }
}

// =====================================================================
extern "C" void kernel_launch(void* const* d_in, const int* in_sizes, int n_in,
                              void* d_out, int out_size) {
    const int*   sidx = (const int*)d_in[0];
    const int*   cidx = (const int*)d_in[1];
    const float* semb = (const float*)d_in[2];
    const float* cemb = (const float*)d_in[3];
    const float* Wq = (const float*)d_in[4];   const float* bq = (const float*)d_in[5];
    const float* Wk = (const float*)d_in[6];   const float* bk = (const float*)d_in[7];
    const float* Wv = (const float*)d_in[8];   const float* bv = (const float*)d_in[9];
    const float* Wo = (const float*)d_in[10];  const float* bo = (const float*)d_in[11];
    const float* g1 = (const float*)d_in[12];  const float* be1 = (const float*)d_in[13];
    const float* W1 = (const float*)d_in[14];  const float* bf1 = (const float*)d_in[15];
    const float* W2 = (const float*)d_in[16];  const float* bf2 = (const float*)d_in[17];
    const float* g2 = (const float*)d_in[18];  const float* be2 = (const float*)d_in[19];
    const float* Wl = (const float*)d_in[20];  const float* bl = (const float*)d_in[21];
    const float* Wp1 = (const float*)d_in[22]; const float* bp1 = (const float*)d_in[23];
    const float* Wp2 = (const float*)d_in[24]; const float* bp2 = (const float*)d_in[25];
    const float* wc = (const float*)d_in[26];  const float* bc = (const float*)d_in[27];
    float* out = (float*)d_out;

    __half *px, *pqkv, *pvt, *pctx, *pt, *pf, *py1;
    __half *pwqkvT, *pwoT, *pw1T, *pw2T;
    float *py2, *pbqkv, *pcompsum, *pkl;
    int *pclosed, *psegstart, *psegend, *pnseg;
    cudaGetSymbolAddress((void**)&px, g_x);
    cudaGetSymbolAddress((void**)&pqkv, g_qkv);
    cudaGetSymbolAddress((void**)&pvt, g_vt);
    cudaGetSymbolAddress((void**)&pctx, g_ctx);
    cudaGetSymbolAddress((void**)&pt, g_t);
    cudaGetSymbolAddress((void**)&pf, g_f);
    cudaGetSymbolAddress((void**)&py1, g_y1);
    cudaGetSymbolAddress((void**)&py2, g_y2);
    cudaGetSymbolAddress((void**)&pwqkvT, g_wqkvT);
    cudaGetSymbolAddress((void**)&pbqkv, g_bqkv);
    cudaGetSymbolAddress((void**)&pwoT, g_woT);
    cudaGetSymbolAddress((void**)&pw1T, g_w1T);
    cudaGetSymbolAddress((void**)&pw2T, g_w2T);
    cudaGetSymbolAddress((void**)&pclosed, g_closed);
    cudaGetSymbolAddress((void**)&psegstart, g_segstart);
    cudaGetSymbolAddress((void**)&psegend, g_segend);
    cudaGetSymbolAddress((void**)&pnseg, g_nseg);
    cudaGetSymbolAddress((void**)&pcompsum, g_compsum);
    cudaGetSymbolAddress((void**)&pkl, g_kl);

    const int SMEM128 = (3*128*32 + 3*128*32) * 4;   // 98304 B (words)
    const int SMEM64  = (3*128*32 + 3*64*32) * 4;    // 73728
    const int SMEMFL  = (4096 + 8192 + 8192 + 8192) * 4;  // 114688
    cudaFuncSetAttribute(k_mma<128>, cudaFuncAttributeMaxDynamicSharedMemorySize, SMEM128);
    cudaFuncSetAttribute(k_mma<64>,  cudaFuncAttributeMaxDynamicSharedMemorySize, SMEM64);
    cudaFuncSetAttribute(k_flash,    cudaFuncAttributeMaxDynamicSharedMemorySize, SMEMFL);

    k_init<<<1, 32>>>(pcompsum, pkl);
    k_bcat<<<1, 256>>>(bq, bk, bv, pbqkv);
    k_embed<<<TOK, Dn>>>(sidx, cidx, semb, cemb, px);

    dim3 tb(32, 8);
    k_transpose_f2h<<<dim3(Dn/32, Dn/32), tb>>>(Wq, Dn, pwqkvT, Dn);
    k_transpose_f2h<<<dim3(Dn/32, Dn/32), tb>>>(Wk, Dn, pwqkvT + Dn*Dn, Dn);
    k_transpose_f2h<<<dim3(Dn/32, Dn/32), tb>>>(Wv, Dn, pwqkvT + 2*Dn*Dn, Dn);
    k_transpose_f2h<<<dim3(Dn/32, Dn/32), tb>>>(Wo, Dn, pwoT, Dn);
    k_transpose_f2h<<<dim3(DFFn/32, Dn/32), tb>>>(W1, DFFn, pw1T, Dn);
    k_transpose_f2h<<<dim3(Dn/32, DFFn/32), tb>>>(W2, Dn, pw2T, DFFn);

    // merged QKV projection: [16384,768] = x @ Wqkv
    k_mma<128><<<dim3(6, TOK/128, 1), 256, SMEM128>>>(px, Dn, pwqkvT, Dn,
                                                      pqkv, LDQ, Dn, pbqkv, 0, 1.f, nullptr);

    // V^T per (b,h): [64][1024] from qkv v-section
    k_transpose_h<<<dim3(DHn/32, Ln/32, Bn*Hn), tb>>>(pqkv + 512, LDQ, 0, (long)Ln*LDQ, DHn,
                                                      pvt, Ln, (long)DHn*Ln);

    // fused flash attention
    k_flash<<<dim3(Ln/128, Bn*Hn), 256, SMEMFL>>>(pqkv, pvt, pctx);

    // attn out proj + residual(x), then LN1 (half out)
    k_mma<64><<<dim3(4, TOK/128, 1), 256, SMEM64>>>(pctx, Dn, pwoT, Dn,
                                                    pt, Dn, Dn, bo, 0, 1.f, px);
    k_ln<<<TOK, Dn>>>(pt, g1, be1, py1, nullptr);

    // FFN (FFN2 fuses residual py1); LN2 writes fp32 y2
    k_mma<128><<<dim3(16, TOK/128, 1), 256, SMEM128>>>(py1, Dn, pw1T, Dn,
                                                       pt, DFFn, Dn, bf1, 1, 1.f, nullptr);
    k_mma<64><<<dim3(4, TOK/128, 1), 256, SMEM64>>>(pt, DFFn, pw2T, DFFn,
                                                    pf, Dn, DFFn, bf2, 0, 1.f, py1);
    k_ln<<<TOK, Dn>>>(pf, g2, be2, nullptr, py2);

    // logits / KL / boundaries / segments (fp32 path)
    k_logits<<<TOK/8, 256>>>(py2, Wl, bl, pclosed, pkl);
    k_segscan<<<1, Bn>>>(pclosed, psegstart, psegend, pnseg);

    dim3 gSeg(Ln/8, Bn, 1);
    k_segpred8<<<gSeg, 256>>>(py2, Wp1, bp1, Wp2, bp2, wc, bc,
                              psegstart, psegend, pnseg, pcompsum);

    k_final<<<1, 32>>>(pcompsum, pnseg, pkl, out);

    (void)in_sizes; (void)n_in; (void)out_size;
}

// round 14
// speedup vs baseline: 1.0073x; 1.0073x over previous
#include <cuda_runtime.h>
#include <cuda_fp16.h>
#include <math.h>
#include <stdint.h>

// Problem dims
#define Bn   16
#define Ln   1024
#define Dn   256
#define Hn   4
#define DHn  64
#define DFFn 2048
#define Cn   3
#define TOK  (Bn*Ln)          // 16384
#define LDQ  768              // qkv combined row stride

// ---------------- scratch (device globals; no allocations) ----------------
__device__ __half g_x[TOK*Dn];
__device__ __half g_qkv[TOK*LDQ];                 // q|k|v concatenated per token
__device__ __half g_vt[TOK*Dn];                   // V^T per (b,h): [64][1024]
__device__ __half g_ctx[TOK*Dn];
__device__ __half g_t[TOK*DFFn];                  // proj temp + FF hidden
__device__ __half g_f[TOK*Dn];
__device__ __half g_y1[TOK*Dn];
__device__ float  g_y2[TOK*Dn];                   // fp32: drives argmax/segments
__device__ __half g_wqkvT[3*Dn*Dn];               // [768][256]
__device__ float  g_bqkv[3*Dn];
__device__ __half g_woT[Dn*Dn];
__device__ __half g_w1T[Dn*DFFn];
__device__ __half g_w2T[Dn*DFFn];
__device__ int    g_closed[TOK];
__device__ int    g_segstart[TOK];
__device__ int    g_segend[TOK];
__device__ int    g_nseg[Bn];
__device__ float  g_compsum[Bn];
__device__ float  g_kl[1];

// ---------------- helpers ----------------
__device__ __forceinline__ void mma_f16(float d[4],
                                        uint32_t a0, uint32_t a1, uint32_t a2, uint32_t a3,
                                        uint32_t b0, uint32_t b1) {
    asm volatile(
        "mma.sync.aligned.m16n8k16.row.col.f32.f16.f16.f32 "
        "{%0,%1,%2,%3}, {%4,%5,%6,%7}, {%8,%9}, {%0,%1,%2,%3};"
        : "+f"(d[0]), "+f"(d[1]), "+f"(d[2]), "+f"(d[3])
        : "r"(a0), "r"(a1), "r"(a2), "r"(a3), "r"(b0), "r"(b1));
}

__device__ __forceinline__ void cp16(void* smem_dst, const void* gsrc) {
    uint32_t d = (uint32_t)__cvta_generic_to_shared(smem_dst);
    asm volatile("cp.async.cg.shared.global [%0], [%1], 16;" :: "r"(d), "l"(gsrc));
}
#define CP_COMMIT() asm volatile("cp.async.commit_group;" ::: "memory")
#define CP_WAIT(n)  asm volatile("cp.async.wait_group %0;" :: "n"(n) : "memory")

// ======================= HMMA FP16 GEMM (3-stage cp.async pipeline) ================
// C[128,BN](half) = alpha * A[M,K](half) @ Bt[N,K]^T(half) (+bias fp32)(+relu)(+resid half)
// K chunks of 64 halfs (128B/row), 4 k-steps of 16. SMEM word layout identical to the
// proven tf32 kernel: rows of 32 uint32 words, group-swizzle g^=(r&7).
template<int BN>
__global__ __launch_bounds__(256, 2)
void k_mma(const __half* __restrict__ A, int lda,
           const __half* __restrict__ Bt, int ldb,
           __half* __restrict__ Cm, int ldc,
           int K, const float* __restrict__ bias, int relu, float alpha,
           const __half* __restrict__ resid)
{
    constexpr int WARPS_M = (BN == 128) ? 2 : 4;
    constexpr int WARPS_N = 8 / WARPS_M;
    constexpr int WM = 128 / WARPS_M;
    constexpr int WN = BN / WARPS_N;
    constexpr int MT = WM / 16;
    constexpr int NT = WN / 8;
    constexpr int BLOADS = BN / 32;

    extern __shared__ uint32_t smw[];
    uint32_t* As = smw;                       // [3][128*32] words
    uint32_t* Bs = smw + 3 * 128 * 32;        // [3][BN*32] words

    int tid = threadIdx.x;
    int row0 = blockIdx.y * 128;
    int col0 = blockIdx.x * BN;

    int w = tid >> 5, lane = tid & 31;
    int wm = w % WARPS_M, wn = w / WARPS_M;
    int lr = lane >> 2, lc = lane & 3;

    float acc[MT][NT][4];
    #pragma unroll
    for (int i = 0; i < MT; i++)
        #pragma unroll
        for (int j = 0; j < NT; j++)
            #pragma unroll
            for (int t = 0; t < 4; t++) acc[i][j][t] = 0.f;

    const int NC = K >> 6;   // chunks of 64 halfs

    auto issue = [&](int c, int buf) {
        int k0 = c << 6;
        #pragma unroll
        for (int i = 0; i < 4; i++) {
            int idx = tid + 256 * i;
            int r = idx >> 3, g = idx & 7;
            int gs = g ^ (r & 7);
            cp16(As + buf*128*32 + r*32 + gs*4,
                 &A[(size_t)(row0 + r) * lda + k0 + g*8]);
        }
        #pragma unroll
        for (int i = 0; i < BLOADS; i++) {
            int idx = tid + 256 * i;
            int r = idx >> 3, g = idx & 7;
            int gs = g ^ (r & 7);
            cp16(Bs + buf*BN*32 + r*32 + gs*4,
                 &Bt[(size_t)(col0 + r) * ldb + k0 + g*8]);
        }
    };

    issue(0, 0); CP_COMMIT();
    if (NC > 1) { issue(1, 1); CP_COMMIT(); }

    for (int c = 0; c < NC; c++) {
        if (c + 1 < NC) CP_WAIT(1); else CP_WAIT(0);
        __syncthreads();
        if (c + 2 < NC) { issue(c + 2, (c + 2) % 3); CP_COMMIT(); }

        int buf = c % 3;
        const uint32_t* Au = As + buf * 128 * 32;
        const uint32_t* Bu = Bs + buf * BN * 32;
        #pragma unroll
        for (int ks = 0; ks < 4; ks++) {
            uint32_t af[MT][4];
            #pragma unroll
            for (int mt = 0; mt < MT; mt++) {
                int arow = wm * WM + mt * 16 + lr;
                int sw = (arow & 7);
                const uint32_t* base = Au + arow * 32;
                af[mt][0] = base[(((2*ks)   ^ sw) << 2) + lc];
                af[mt][2] = base[(((2*ks+1) ^ sw) << 2) + lc];
                const uint32_t* base8 = Au + (arow + 8) * 32;
                af[mt][1] = base8[(((2*ks)   ^ sw) << 2) + lc];
                af[mt][3] = base8[(((2*ks+1) ^ sw) << 2) + lc];
            }
            uint32_t bf[NT][2];
            #pragma unroll
            for (int nt = 0; nt < NT; nt++) {
                int brow = wn * WN + nt * 8 + lr;
                int sw = (brow & 7);
                const uint32_t* base = Bu + brow * 32;
                bf[nt][0] = base[(((2*ks)   ^ sw) << 2) + lc];
                bf[nt][1] = base[(((2*ks+1) ^ sw) << 2) + lc];
            }
            #pragma unroll
            for (int mt = 0; mt < MT; mt++)
                #pragma unroll
                for (int nt = 0; nt < NT; nt++)
                    mma_f16(acc[mt][nt], af[mt][0], af[mt][1], af[mt][2], af[mt][3],
                            bf[nt][0], bf[nt][1]);
        }
    }

    #pragma unroll
    for (int mt = 0; mt < MT; mt++) {
        int row = row0 + wm * WM + mt * 16 + lr;
        #pragma unroll
        for (int nt = 0; nt < NT; nt++) {
            int col = col0 + wn * WN + nt * 8 + 2 * lc;
            float v0 = acc[mt][nt][0] * alpha, v1 = acc[mt][nt][1] * alpha;
            float v2 = acc[mt][nt][2] * alpha, v3 = acc[mt][nt][3] * alpha;
            if (bias) {
                float b0 = bias[col], b1 = bias[col + 1];
                v0 += b0; v1 += b1; v2 += b0; v3 += b1;
            }
            if (resid) {
                float2 r0 = __half22float2(*(const __half2*)&resid[(size_t)row * ldc + col]);
                float2 r1 = __half22float2(*(const __half2*)&resid[(size_t)(row + 8) * ldc + col]);
                v0 += r0.x; v1 += r0.y; v2 += r1.x; v3 += r1.y;
            }
            if (relu) {
                v0 = fmaxf(v0, 0.f); v1 = fmaxf(v1, 0.f);
                v2 = fmaxf(v2, 0.f); v3 = fmaxf(v3, 0.f);
            }
            *(__half2*)&Cm[(size_t)row * ldc + col] = __floats2half2_rn(v0, v1);
            *(__half2*)&Cm[(size_t)(row + 8) * ldc + col] = __floats2half2_rn(v2, v3);
        }
    }
}

// ======================= fused flash attention (fp16 operands) =====================
// One CTA per (128-query tile, b*4+h). 8 warps, warp = 16 query rows.
// SMEM (uint32 words): Qs 128*32, Ks 2x128*32, Vs 2x64*64, Ps 128*64 = 112 KB.
__global__ __launch_bounds__(256, 1)
void k_flash(const __half* __restrict__ QKV, const __half* __restrict__ Vt,
             __half* __restrict__ O)
{
    extern __shared__ uint32_t us[];
    uint32_t* Qs = us;                   // 128 rows x 32 words
    uint32_t* Ks = us + 4096;            // 2 x 128 x 32
    uint32_t* Vs = us + 12288;           // 2 x 64 x 64
    uint32_t* Ps = us + 20480;           // 128 x 64

    int z = blockIdx.y;
    const __half* q  = QKV + (size_t)(z>>2)*Ln*LDQ + (size_t)(z&3)*DHn;
    const __half* kp = q + 256;
    const __half* vt = Vt + (size_t)z*DHn*Ln;
    __half* o        = O  + (size_t)(z>>2)*Ln*Dn + (size_t)(z&3)*DHn;

    int row0 = blockIdx.x * 128;
    int tid = threadIdx.x, w = tid >> 5, lane = tid & 31;
    int lr = lane >> 2, lc = lane & 3;

    auto issueK = [&](int j, int buf) {
        #pragma unroll
        for (int i = 0; i < 4; i++) {
            int idx = tid + 256*i;
            int r = idx >> 3, g = idx & 7;
            cp16(Ks + buf*4096 + r*32 + ((g ^ (r & 7)) << 2),
                 &kp[(size_t)(j*128 + r)*LDQ + g*8]);
        }
    };
    auto issueV = [&](int j, int buf) {
        #pragma unroll
        for (int i = 0; i < 4; i++) {
            int idx = tid + 256*i;
            int r = idx >> 4, g = idx & 15;
            cp16(Vs + buf*4096 + r*64 + ((g ^ (r & 7)) << 2),
                 &vt[(size_t)r*Ln + j*128 + g*8]);
        }
    };

    #pragma unroll
    for (int i = 0; i < 4; i++) {
        int idx = tid + 256*i;
        int r = idx >> 3, g = idx & 7;
        cp16(Qs + r*32 + ((g ^ (r & 7)) << 2),
             &q[(size_t)(row0 + r)*LDQ + g*8]);
    }
    issueK(0, 0); issueV(0, 0);
    CP_COMMIT();

    float m0 = -1e30f, m1 = -1e30f, l0 = 0.f, l1 = 0.f;
    float oa[8][4];
    #pragma unroll
    for (int n = 0; n < 8; n++)
        #pragma unroll
        for (int t = 0; t < 4; t++) oa[n][t] = 0.f;

    int arow = w*16 + lr;
    int asw = arow & 7;

    for (int j = 0; j < 8; j++) {
        if (j + 1 < 8) {
            issueK(j + 1, (j + 1) & 1); issueV(j + 1, (j + 1) & 1);
            CP_COMMIT();
            CP_WAIT(1);
        } else {
            CP_WAIT(0);
        }
        __syncthreads();

        const uint32_t* Kb = Ks + (j & 1)*4096;
        const uint32_t* Vb = Vs + (j & 1)*4096;

        // ---- S = Q @ K^T  (k = 64 halfs -> 4 k-steps of 16) ----
        float sacc[16][4];
        #pragma unroll
        for (int n = 0; n < 16; n++)
            #pragma unroll
            for (int t = 0; t < 4; t++) sacc[n][t] = 0.f;

        #pragma unroll
        for (int ks = 0; ks < 4; ks++) {
            const uint32_t* ab  = Qs + arow*32;
            const uint32_t* ab8 = Qs + (arow + 8)*32;
            uint32_t a0 = ab [(((2*ks)   ^ asw) << 2) + lc];
            uint32_t a2 = ab [(((2*ks+1) ^ asw) << 2) + lc];
            uint32_t a1 = ab8[(((2*ks)   ^ asw) << 2) + lc];
            uint32_t a3 = ab8[(((2*ks+1) ^ asw) << 2) + lc];
            #pragma unroll
            for (int nt = 0; nt < 16; nt++) {
                int brow = nt*8 + lr;
                int bsw = brow & 7;
                const uint32_t* bb = Kb + brow*32;
                uint32_t b0 = bb[(((2*ks)   ^ bsw) << 2) + lc];
                uint32_t b1 = bb[(((2*ks+1) ^ bsw) << 2) + lc];
                mma_f16(sacc[nt], a0, a1, a2, a3, b0, b1);
            }
        }

        // ---- online softmax ----
        float rm0 = -1e30f, rm1 = -1e30f;
        #pragma unroll
        for (int nt = 0; nt < 16; nt++) {
            #pragma unroll
            for (int t = 0; t < 4; t++) sacc[nt][t] *= 0.125f;
            rm0 = fmaxf(rm0, fmaxf(sacc[nt][0], sacc[nt][1]));
            rm1 = fmaxf(rm1, fmaxf(sacc[nt][2], sacc[nt][3]));
        }
        rm0 = fmaxf(rm0, __shfl_xor_sync(0xffffffff, rm0, 1));
        rm0 = fmaxf(rm0, __shfl_xor_sync(0xffffffff, rm0, 2));
        rm1 = fmaxf(rm1, __shfl_xor_sync(0xffffffff, rm1, 1));
        rm1 = fmaxf(rm1, __shfl_xor_sync(0xffffffff, rm1, 2));
        float mn0 = fmaxf(m0, rm0), mn1 = fmaxf(m1, rm1);
        float sc0 = expf(m0 - mn0), sc1 = expf(m1 - mn1);

        float rs0 = 0.f, rs1 = 0.f;
        #pragma unroll
        for (int nt = 0; nt < 16; nt++) {
            float p0 = expf(sacc[nt][0] - mn0);
            float p1 = expf(sacc[nt][1] - mn0);
            float p2 = expf(sacc[nt][2] - mn1);
            float p3 = expf(sacc[nt][3] - mn1);
            rs0 += p0 + p1; rs1 += p2 + p3;
            // P store: col pair (nt*8+2lc, +1) -> word nt*4+lc -> group nt, word lc
            *(__half2*)(Ps + arow*64 + ((nt ^ asw) << 2) + lc) = __floats2half2_rn(p0, p1);
            *(__half2*)(Ps + (arow + 8)*64 + ((nt ^ asw) << 2) + lc) = __floats2half2_rn(p2, p3);
        }
        rs0 += __shfl_xor_sync(0xffffffff, rs0, 1);
        rs0 += __shfl_xor_sync(0xffffffff, rs0, 2);
        rs1 += __shfl_xor_sync(0xffffffff, rs1, 1);
        rs1 += __shfl_xor_sync(0xffffffff, rs1, 2);
        l0 = l0*sc0 + rs0; l1 = l1*sc1 + rs1;
        m0 = mn0; m1 = mn1;
        #pragma unroll
        for (int nt = 0; nt < 8; nt++) {
            oa[nt][0] *= sc0; oa[nt][1] *= sc0;
            oa[nt][2] *= sc1; oa[nt][3] *= sc1;
        }
        __syncwarp();

        // ---- O += P @ V^T  (k = 128 halfs -> 8 k-steps of 16) ----
        #pragma unroll
        for (int ks = 0; ks < 8; ks++) {
            const uint32_t* ab  = Ps + arow*64;
            const uint32_t* ab8 = Ps + (arow + 8)*64;
            uint32_t a0 = ab [(((2*ks)   ^ asw) << 2) + lc];
            uint32_t a2 = ab [(((2*ks+1) ^ asw) << 2) + lc];
            uint32_t a1 = ab8[(((2*ks)   ^ asw) << 2) + lc];
            uint32_t a3 = ab8[(((2*ks+1) ^ asw) << 2) + lc];
            #pragma unroll
            for (int nt = 0; nt < 8; nt++) {
                int brow = nt*8 + lr;
                int bsw = brow & 7;
                const uint32_t* bb = Vb + brow*64;
                uint32_t b0 = bb[(((2*ks)   ^ bsw) << 2) + lc];
                uint32_t b1 = bb[(((2*ks+1) ^ bsw) << 2) + lc];
                mma_f16(oa[nt], a0, a1, a2, a3, b0, b1);
            }
        }
        __syncthreads();
    }

    float il0 = 1.f / l0, il1 = 1.f / l1;
    int row = row0 + w*16 + lr;
    #pragma unroll
    for (int nt = 0; nt < 8; nt++) {
        int col = nt*8 + 2*lc;
        *(__half2*)&o[(size_t)row*Dn + col] =
            __floats2half2_rn(oa[nt][0]*il0, oa[nt][1]*il0);
        *(__half2*)&o[(size_t)(row + 8)*Dn + col] =
            __floats2half2_rn(oa[nt][2]*il1, oa[nt][3]*il1);
    }
}

// ======================= transposes =======================
__global__ void k_transpose_f2h(const float* __restrict__ in, int ldin,
                                __half* __restrict__ out, int ldout)
{
    __shared__ float tile[32][33];
    int c0 = blockIdx.x*32, r0 = blockIdx.y*32;
    int tx = threadIdx.x, ty = threadIdx.y;   // 32 x 8
    #pragma unroll
    for (int i = 0; i < 32; i += 8)
        tile[ty+i][tx] = in[(size_t)(r0+ty+i)*ldin + c0+tx];
    __syncthreads();
    #pragma unroll
    for (int i = 0; i < 32; i += 8)
        out[(size_t)(c0+ty+i)*ldout + r0+tx] = __float2half(tile[tx][ty+i]);
}

// half->half transpose with per-z offsets (for V^T): off = z*iS1 + (z>>2)*iS2 + (z&3)*iS3
__global__ void k_transpose_h(const __half* __restrict__ in, int ldin,
                              long iS1, long iS2, long iS3,
                              __half* __restrict__ out, int ldout, long oS1)
{
    __shared__ __half tile[32][34];
    int z = blockIdx.z;
    in  += (long)z*iS1 + (long)(z>>2)*iS2 + (long)(z&3)*iS3;
    out += (long)z*oS1;
    int c0 = blockIdx.x*32, r0 = blockIdx.y*32;
    int tx = threadIdx.x, ty = threadIdx.y;   // 32 x 8
    #pragma unroll
    for (int i = 0; i < 32; i += 8)
        tile[ty+i][tx] = in[(size_t)(r0+ty+i)*ldin + c0+tx];
    __syncthreads();
    #pragma unroll
    for (int i = 0; i < 32; i += 8)
        out[(size_t)(c0+ty+i)*ldout + r0+tx] = tile[tx][ty+i];
}

// ---------------- init / bias concat ----------------
__global__ void k_init(float* compsum, float* kl) {
    int t = threadIdx.x;
    if (t < Bn) compsum[t] = 0.f;
    if (t == 0) kl[0] = 0.f;
}
__global__ void k_bcat(const float* bq, const float* bk, const float* bv, float* o) {
    int t = threadIdx.x;
    o[t] = bq[t]; o[256 + t] = bk[t]; o[512 + t] = bv[t];
}

// ---------------- embedding (half out) ----------------
__global__ void k_embed(const int* __restrict__ sidx, const int* __restrict__ cidx,
                        const float* __restrict__ semb, const float* __restrict__ cemb,
                        __half* __restrict__ x) {
    int tok = blockIdx.x;
    int d = threadIdx.x;
    int si = sidx[tok], ci = cidx[tok];
    x[(size_t)tok*Dn + d] = __float2half(semb[si*Dn + d] + cemb[ci*Dn + d]);
}

// ---------------- LayerNorm (half in; half and/or float out) ----------------
__global__ void k_ln(const __half* __restrict__ T,
                     const float* __restrict__ g, const float* __restrict__ b,
                     __half* __restrict__ Yh, float* __restrict__ Yf) {
    int row = blockIdx.x, d = threadIdx.x;
    __shared__ float red[256];
    float v = __half2float(T[(size_t)row*Dn + d]);
    red[d] = v; __syncthreads();
    for (int o = 128; o > 0; o >>= 1) { if (d < o) red[d] += red[d+o]; __syncthreads(); }
    float m = red[0] * (1.f / Dn); __syncthreads();
    float dv = v - m;
    red[d] = dv * dv; __syncthreads();
    for (int o = 128; o > 0; o >>= 1) { if (d < o) red[d] += red[d+o]; __syncthreads(); }
    float var = red[0] * (1.f / Dn);
    float y = dv * rsqrtf(var + 1e-5f) * g[d] + b[d];
    if (Yh) Yh[(size_t)row*Dn + d] = __float2half(y);
    if (Yf) Yf[(size_t)row*Dn + d] = y;
}

// ---------------- logits + KL + boundary (fp32 y2) ----------------
__global__ void k_logits(const float* __restrict__ Y, const float* __restrict__ Wl,
                         const float* __restrict__ bl, int* __restrict__ closed,
                         float* __restrict__ klacc) {
    int warp = (blockIdx.x * blockDim.x + threadIdx.x) >> 5;
    int lane = threadIdx.x & 31;
    if (warp >= TOK) return;
    const float* y = Y + (size_t)warp * Dn;
    float l0 = 0.f, l1 = 0.f, l2 = 0.f;
    #pragma unroll
    for (int i = 0; i < 8; i++) {
        int d = lane + i * 32;
        float yv = y[d];
        l0 += yv * Wl[d*3 + 0];
        l1 += yv * Wl[d*3 + 1];
        l2 += yv * Wl[d*3 + 2];
    }
    #pragma unroll
    for (int o = 16; o > 0; o >>= 1) {
        l0 += __shfl_xor_sync(0xffffffff, l0, o);
        l1 += __shfl_xor_sync(0xffffffff, l1, o);
        l2 += __shfl_xor_sync(0xffffffff, l2, o);
    }
    if (lane == 0) {
        l0 += bl[0]; l1 += bl[1]; l2 += bl[2];
        float mx = fmaxf(l0, fmaxf(l1, l2));
        float lse = logf(expf(l0-mx) + expf(l1-mx) + expf(l2-mx)) + mx;
        float sumlogp = (l0 + l1 + l2) - 3.f * lse;
        atomicAdd(klacc, sumlogp);
        int l = warp & (Ln - 1);
        int boundary = (l0 >= l1 && l0 >= l2) ? 1 : 0;
        closed[warp] = (boundary && l > 0) ? 1 : 0;
    }
}

// ---------------- per-batch serial segment scan ----------------
__global__ void k_segscan(const int* __restrict__ closed, int* __restrict__ sstart,
                          int* __restrict__ send, int* __restrict__ nseg) {
    int b = threadIdx.x;
    if (b >= Bn) return;
    int cnt = 0, start = 0;
    for (int l = 0; l < Ln; l++) {
        if (closed[b*Ln + l]) {
            sstart[b*Ln + cnt] = start;
            send[b*Ln + cnt] = l;
            cnt++; start = l + 1;
        }
    }
    if (start <= Ln - 1) {
        sstart[b*Ln + cnt] = start;
        send[b*Ln + cnt] = Ln - 1;
        cnt++;
    }
    nseg[b] = cnt;
}

// ---------------- segment mean + predicate net, 8 segments per block ----------------
__global__ void k_segpred8(const float* __restrict__ Y, const float* __restrict__ Wp1,
                           const float* __restrict__ bp1, const float* __restrict__ Wp2,
                           const float* __restrict__ bp2, const float* __restrict__ wc,
                           const float* __restrict__ bc,
                           const int* __restrict__ sstart, const int* __restrict__ send,
                           const int* __restrict__ nseg, float* __restrict__ compsum) {
    int b = blockIdx.y;
    int ns = nseg[b];
    int s0 = blockIdx.x * 8;
    if (s0 >= ns) return;
    int cnt = min(8, ns - s0);
    int d = threadIdx.x;
    __shared__ float mean[8][256];
    for (int s = 0; s < cnt; s++) {
        int st = sstart[b*Ln + s0 + s], en = send[b*Ln + s0 + s];
        float sum = 0.f;
        for (int l = st; l <= en; l++)
            sum += Y[((size_t)(b*Ln + l)) * Dn + d];
        mean[s][d] = sum / (float)(en - st + 1);
    }
    for (int s = cnt; s < 8; s++) mean[s][d] = 0.f;
    __syncthreads();

    float acc[8];
    float bp = bp1[d];
    #pragma unroll
    for (int s = 0; s < 8; s++) acc[s] = bp;
    for (int k = 0; k < Dn; k++) {
        float w = Wp1[k*Dn + d];
        #pragma unroll
        for (int s = 0; s < 8; s++) acc[s] += mean[s][k] * w;
    }

    float w2 = Wp2[d];
    __shared__ float red[256];
    __shared__ float comp_total;
    if (d == 0) comp_total = 0.f;
    __syncthreads();
    for (int s = 0; s < cnt; s++) {
        red[d] = fmaxf(acc[s], 0.f) * w2;
        __syncthreads();
        for (int o = 128; o > 0; o >>= 1) { if (d < o) red[d] += red[d+o]; __syncthreads(); }
        if (d == 0) {
            float pin = red[0] + bp2[0];
            float sig = 1.f / (1.f + expf(-pin));
            comp_total += sig * wc[0] + bc[0];
        }
        __syncthreads();
    }
    if (d == 0) atomicAdd(&compsum[b], comp_total);
}

// ---------------- final outputs ----------------
__global__ void k_final(const float* __restrict__ compsum, const int* __restrict__ nseg,
                        const float* __restrict__ kl, float* __restrict__ out) {
    int t = threadIdx.x;
    if (t < Bn) {
        float mc = compsum[t] / (float)nseg[t];
        out[t] = 1.f / (1.f + expf(-mc));
    }
    if (t == Bn) {
        out[Bn] = ((float)TOK * logf(1.f/3.f) - (1.f/3.f) * kl[0]) / (float)Bn;
    }
}

// =====================================================================
extern "C" void kernel_launch(void* const* d_in, const int* in_sizes, int n_in,
                              void* d_out, int out_size) {
    const int*   sidx = (const int*)d_in[0];
    const int*   cidx = (const int*)d_in[1];
    const float* semb = (const float*)d_in[2];
    const float* cemb = (const float*)d_in[3];
    const float* Wq = (const float*)d_in[4];   const float* bq = (const float*)d_in[5];
    const float* Wk = (const float*)d_in[6];   const float* bk = (const float*)d_in[7];
    const float* Wv = (const float*)d_in[8];   const float* bv = (const float*)d_in[9];
    const float* Wo = (const float*)d_in[10];  const float* bo = (const float*)d_in[11];
    const float* g1 = (const float*)d_in[12];  const float* be1 = (const float*)d_in[13];
    const float* W1 = (const float*)d_in[14];  const float* bf1 = (const float*)d_in[15];
    const float* W2 = (const float*)d_in[16];  const float* bf2 = (const float*)d_in[17];
    const float* g2 = (const float*)d_in[18];  const float* be2 = (const float*)d_in[19];
    const float* Wl = (const float*)d_in[20];  const float* bl = (const float*)d_in[21];
    const float* Wp1 = (const float*)d_in[22]; const float* bp1 = (const float*)d_in[23];
    const float* Wp2 = (const float*)d_in[24]; const float* bp2 = (const float*)d_in[25];
    const float* wc = (const float*)d_in[26];  const float* bc = (const float*)d_in[27];
    float* out = (float*)d_out;

    __half *px, *pqkv, *pvt, *pctx, *pt, *pf, *py1;
    __half *pwqkvT, *pwoT, *pw1T, *pw2T;
    float *py2, *pbqkv, *pcompsum, *pkl;
    int *pclosed, *psegstart, *psegend, *pnseg;
    cudaGetSymbolAddress((void**)&px, g_x);
    cudaGetSymbolAddress((void**)&pqkv, g_qkv);
    cudaGetSymbolAddress((void**)&pvt, g_vt);
    cudaGetSymbolAddress((void**)&pctx, g_ctx);
    cudaGetSymbolAddress((void**)&pt, g_t);
    cudaGetSymbolAddress((void**)&pf, g_f);
    cudaGetSymbolAddress((void**)&py1, g_y1);
    cudaGetSymbolAddress((void**)&py2, g_y2);
    cudaGetSymbolAddress((void**)&pwqkvT, g_wqkvT);
    cudaGetSymbolAddress((void**)&pbqkv, g_bqkv);
    cudaGetSymbolAddress((void**)&pwoT, g_woT);
    cudaGetSymbolAddress((void**)&pw1T, g_w1T);
    cudaGetSymbolAddress((void**)&pw2T, g_w2T);
    cudaGetSymbolAddress((void**)&pclosed, g_closed);
    cudaGetSymbolAddress((void**)&psegstart, g_segstart);
    cudaGetSymbolAddress((void**)&psegend, g_segend);
    cudaGetSymbolAddress((void**)&pnseg, g_nseg);
    cudaGetSymbolAddress((void**)&pcompsum, g_compsum);
    cudaGetSymbolAddress((void**)&pkl, g_kl);

    const int SMEM128 = (3*128*32 + 3*128*32) * 4;   // 98304 B (words)
    const int SMEM64  = (3*128*32 + 3*64*32) * 4;    // 73728
    const int SMEMFL  = (4096 + 8192 + 8192 + 8192) * 4;  // 114688
    cudaFuncSetAttribute(k_mma<128>, cudaFuncAttributeMaxDynamicSharedMemorySize, SMEM128);
    cudaFuncSetAttribute(k_mma<64>,  cudaFuncAttributeMaxDynamicSharedMemorySize, SMEM64);
    cudaFuncSetAttribute(k_flash,    cudaFuncAttributeMaxDynamicSharedMemorySize, SMEMFL);

    k_init<<<1, 32>>>(pcompsum, pkl);
    k_bcat<<<1, 256>>>(bq, bk, bv, pbqkv);
    k_embed<<<TOK, Dn>>>(sidx, cidx, semb, cemb, px);

    dim3 tb(32, 8);
    k_transpose_f2h<<<dim3(Dn/32, Dn/32), tb>>>(Wq, Dn, pwqkvT, Dn);
    k_transpose_f2h<<<dim3(Dn/32, Dn/32), tb>>>(Wk, Dn, pwqkvT + Dn*Dn, Dn);
    k_transpose_f2h<<<dim3(Dn/32, Dn/32), tb>>>(Wv, Dn, pwqkvT + 2*Dn*Dn, Dn);
    k_transpose_f2h<<<dim3(Dn/32, Dn/32), tb>>>(Wo, Dn, pwoT, Dn);
    k_transpose_f2h<<<dim3(DFFn/32, Dn/32), tb>>>(W1, DFFn, pw1T, Dn);
    k_transpose_f2h<<<dim3(Dn/32, DFFn/32), tb>>>(W2, Dn, pw2T, DFFn);

    // merged QKV projection: [16384,768] = x @ Wqkv
    k_mma<128><<<dim3(6, TOK/128, 1), 256, SMEM128>>>(px, Dn, pwqkvT, Dn,
                                                      pqkv, LDQ, Dn, pbqkv, 0, 1.f, nullptr);

    // V^T per (b,h): [64][1024] from qkv v-section
    k_transpose_h<<<dim3(DHn/32, Ln/32, Bn*Hn), tb>>>(pqkv + 512, LDQ, 0, (long)Ln*LDQ, DHn,
                                                      pvt, Ln, (long)DHn*Ln);

    // fused flash attention
    k_flash<<<dim3(Ln/128, Bn*Hn), 256, SMEMFL>>>(pqkv, pvt, pctx);

    // attn out proj + residual(x), then LN1 (half out)
    k_mma<64><<<dim3(4, TOK/128, 1), 256, SMEM64>>>(pctx, Dn, pwoT, Dn,
                                                    pt, Dn, Dn, bo, 0, 1.f, px);
    k_ln<<<TOK, Dn>>>(pt, g1, be1, py1, nullptr);

    // FFN (FFN2 fuses residual py1); LN2 writes fp32 y2
    k_mma<128><<<dim3(16, TOK/128, 1), 256, SMEM128>>>(py1, Dn, pw1T, Dn,
                                                       pt, DFFn, Dn, bf1, 1, 1.f, nullptr);
    k_mma<64><<<dim3(4, TOK/128, 1), 256, SMEM64>>>(pt, DFFn, pw2T, DFFn,
                                                    pf, Dn, DFFn, bf2, 0, 1.f, py1);
    k_ln<<<TOK, Dn>>>(pf, g2, be2, nullptr, py2);

    // logits / KL / boundaries / segments (fp32 path)
    k_logits<<<TOK/8, 256>>>(py2, Wl, bl, pclosed, pkl);
    k_segscan<<<1, Bn>>>(pclosed, psegstart, psegend, pnseg);

    dim3 gSeg(Ln/8, Bn, 1);
    k_segpred8<<<gSeg, 256>>>(py2, Wp1, bp1, Wp2, bp2, wc, bc,
                              psegstart, psegend, pnseg, pcompsum);

    k_final<<<1, 32>>>(pcompsum, pnseg, pkl, out);

    (void)in_sizes; (void)n_in; (void)out_size;
}

// round 15
// speedup vs baseline: 1.0082x; 1.0009x over previous
#include <cuda_runtime.h>
#include <cuda_fp16.h>
#include <math.h>
#include <stdint.h>

// Problem dims
#define Bn   16
#define Ln   1024
#define Dn   256
#define Hn   4
#define DHn  64
#define DFFn 2048
#define Cn   3
#define TOK  (Bn*Ln)          // 16384
#define LDQ  768              // qkv combined row stride

// ---------------- scratch (device globals; no allocations) ----------------
__device__ __half g_x[TOK*Dn];
__device__ __half g_qkv[TOK*LDQ];                 // q|k|v concatenated per token
__device__ __half g_vt[TOK*Dn];                   // V^T per (b,h): [64][1024]
__device__ __half g_ctx[TOK*Dn];
__device__ __half g_t[TOK*DFFn];                  // proj temp + FF hidden
__device__ __half g_f[TOK*Dn];
__device__ __half g_y1[TOK*Dn];
__device__ float  g_y2[TOK*Dn];                   // fp32: drives argmax/segments
__device__ __half g_wqkvT[3*Dn*Dn];               // [768][256]
__device__ float  g_bqkv[3*Dn];
__device__ __half g_woT[Dn*Dn];
__device__ __half g_w1T[Dn*DFFn];
__device__ __half g_w2T[Dn*DFFn];
__device__ int    g_closed[TOK];
__device__ int    g_segstart[TOK];
__device__ int    g_segend[TOK];
__device__ int    g_nseg[Bn];
__device__ float  g_compsum[Bn];
__device__ float  g_kl[1];

// ---------------- helpers ----------------
__device__ __forceinline__ void mma_f16(float d[4],
                                        uint32_t a0, uint32_t a1, uint32_t a2, uint32_t a3,
                                        uint32_t b0, uint32_t b1) {
    asm volatile(
        "mma.sync.aligned.m16n8k16.row.col.f32.f16.f16.f32 "
        "{%0,%1,%2,%3}, {%4,%5,%6,%7}, {%8,%9}, {%0,%1,%2,%3};"
        : "+f"(d[0]), "+f"(d[1]), "+f"(d[2]), "+f"(d[3])
        : "r"(a0), "r"(a1), "r"(a2), "r"(a3), "r"(b0), "r"(b1));
}

__device__ __forceinline__ void cp16(void* smem_dst, const void* gsrc) {
    uint32_t d = (uint32_t)__cvta_generic_to_shared(smem_dst);
    asm volatile("cp.async.cg.shared.global [%0], [%1], 16;" :: "r"(d), "l"(gsrc));
}
#define CP_COMMIT() asm volatile("cp.async.commit_group;" ::: "memory")
#define CP_WAIT(n)  asm volatile("cp.async.wait_group %0;" :: "n"(n) : "memory")

// ======================= HMMA FP16 GEMM (3-stage cp.async pipeline) ================
// C[128,BN](half) = alpha * A[M,K](half) @ Bt[N,K]^T(half) (+bias fp32)(+relu)(+resid half)
// K chunks of 64 halfs (128B/row), 4 k-steps of 16. SMEM word layout identical to the
// proven tf32 kernel: rows of 32 uint32 words, group-swizzle g^=(r&7).
template<int BN>
__global__ __launch_bounds__(256, 2)
void k_mma(const __half* __restrict__ A, int lda,
           const __half* __restrict__ Bt, int ldb,
           __half* __restrict__ Cm, int ldc,
           int K, const float* __restrict__ bias, int relu, float alpha,
           const __half* __restrict__ resid)
{
    constexpr int WARPS_M = (BN == 128) ? 2 : 4;
    constexpr int WARPS_N = 8 / WARPS_M;
    constexpr int WM = 128 / WARPS_M;
    constexpr int WN = BN / WARPS_N;
    constexpr int MT = WM / 16;
    constexpr int NT = WN / 8;
    constexpr int BLOADS = BN / 32;

    extern __shared__ uint32_t smw[];
    uint32_t* As = smw;                       // [3][128*32] words
    uint32_t* Bs = smw + 3 * 128 * 32;        // [3][BN*32] words

    int tid = threadIdx.x;
    int row0 = blockIdx.y * 128;
    int col0 = blockIdx.x * BN;

    int w = tid >> 5, lane = tid & 31;
    int wm = w % WARPS_M, wn = w / WARPS_M;
    int lr = lane >> 2, lc = lane & 3;

    float acc[MT][NT][4];
    #pragma unroll
    for (int i = 0; i < MT; i++)
        #pragma unroll
        for (int j = 0; j < NT; j++)
            #pragma unroll
            for (int t = 0; t < 4; t++) acc[i][j][t] = 0.f;

    const int NC = K >> 6;   // chunks of 64 halfs

    auto issue = [&](int c, int buf) {
        int k0 = c << 6;
        #pragma unroll
        for (int i = 0; i < 4; i++) {
            int idx = tid + 256 * i;
            int r = idx >> 3, g = idx & 7;
            int gs = g ^ (r & 7);
            cp16(As + buf*128*32 + r*32 + gs*4,
                 &A[(size_t)(row0 + r) * lda + k0 + g*8]);
        }
        #pragma unroll
        for (int i = 0; i < BLOADS; i++) {
            int idx = tid + 256 * i;
            int r = idx >> 3, g = idx & 7;
            int gs = g ^ (r & 7);
            cp16(Bs + buf*BN*32 + r*32 + gs*4,
                 &Bt[(size_t)(col0 + r) * ldb + k0 + g*8]);
        }
    };

    issue(0, 0); CP_COMMIT();
    if (NC > 1) { issue(1, 1); CP_COMMIT(); }

    for (int c = 0; c < NC; c++) {
        if (c + 1 < NC) CP_WAIT(1); else CP_WAIT(0);
        __syncthreads();
        if (c + 2 < NC) { issue(c + 2, (c + 2) % 3); CP_COMMIT(); }

        int buf = c % 3;
        const uint32_t* Au = As + buf * 128 * 32;
        const uint32_t* Bu = Bs + buf * BN * 32;
        #pragma unroll
        for (int ks = 0; ks < 4; ks++) {
            uint32_t af[MT][4];
            #pragma unroll
            for (int mt = 0; mt < MT; mt++) {
                int arow = wm * WM + mt * 16 + lr;
                int sw = (arow & 7);
                const uint32_t* base = Au + arow * 32;
                af[mt][0] = base[(((2*ks)   ^ sw) << 2) + lc];
                af[mt][2] = base[(((2*ks+1) ^ sw) << 2) + lc];
                const uint32_t* base8 = Au + (arow + 8) * 32;
                af[mt][1] = base8[(((2*ks)   ^ sw) << 2) + lc];
                af[mt][3] = base8[(((2*ks+1) ^ sw) << 2) + lc];
            }
            uint32_t bf[NT][2];
            #pragma unroll
            for (int nt = 0; nt < NT; nt++) {
                int brow = wn * WN + nt * 8 + lr;
                int sw = (brow & 7);
                const uint32_t* base = Bu + brow * 32;
                bf[nt][0] = base[(((2*ks)   ^ sw) << 2) + lc];
                bf[nt][1] = base[(((2*ks+1) ^ sw) << 2) + lc];
            }
            #pragma unroll
            for (int mt = 0; mt < MT; mt++)
                #pragma unroll
                for (int nt = 0; nt < NT; nt++)
                    mma_f16(acc[mt][nt], af[mt][0], af[mt][1], af[mt][2], af[mt][3],
                            bf[nt][0], bf[nt][1]);
        }
    }

    #pragma unroll
    for (int mt = 0; mt < MT; mt++) {
        int row = row0 + wm * WM + mt * 16 + lr;
        #pragma unroll
        for (int nt = 0; nt < NT; nt++) {
            int col = col0 + wn * WN + nt * 8 + 2 * lc;
            float v0 = acc[mt][nt][0] * alpha, v1 = acc[mt][nt][1] * alpha;
            float v2 = acc[mt][nt][2] * alpha, v3 = acc[mt][nt][3] * alpha;
            if (bias) {
                float b0 = bias[col], b1 = bias[col + 1];
                v0 += b0; v1 += b1; v2 += b0; v3 += b1;
            }
            if (resid) {
                float2 r0 = __half22float2(*(const __half2*)&resid[(size_t)row * ldc + col]);
                float2 r1 = __half22float2(*(const __half2*)&resid[(size_t)(row + 8) * ldc + col]);
                v0 += r0.x; v1 += r0.y; v2 += r1.x; v3 += r1.y;
            }
            if (relu) {
                v0 = fmaxf(v0, 0.f); v1 = fmaxf(v1, 0.f);
                v2 = fmaxf(v2, 0.f); v3 = fmaxf(v3, 0.f);
            }
            *(__half2*)&Cm[(size_t)row * ldc + col] = __floats2half2_rn(v0, v1);
            *(__half2*)&Cm[(size_t)(row + 8) * ldc + col] = __floats2half2_rn(v2, v3);
        }
    }
}

// ======================= fused flash attention (fp16 operands) =====================
// One CTA per (128-query tile, b*4+h). 8 warps, warp = 16 query rows.
// SMEM (uint32 words): Qs 128*32, Ks 2x128*32, Vs 2x64*64, Ps 128*64 = 112 KB.
__global__ __launch_bounds__(256, 1)
void k_flash(const __half* __restrict__ QKV, const __half* __restrict__ Vt,
             __half* __restrict__ O)
{
    extern __shared__ uint32_t us[];
    uint32_t* Qs = us;                   // 128 rows x 32 words
    uint32_t* Ks = us + 4096;            // 2 x 128 x 32
    uint32_t* Vs = us + 12288;           // 2 x 64 x 64
    uint32_t* Ps = us + 20480;           // 128 x 64

    int z = blockIdx.y;
    const __half* q  = QKV + (size_t)(z>>2)*Ln*LDQ + (size_t)(z&3)*DHn;
    const __half* kp = q + 256;
    const __half* vt = Vt + (size_t)z*DHn*Ln;
    __half* o        = O  + (size_t)(z>>2)*Ln*Dn + (size_t)(z&3)*DHn;

    int row0 = blockIdx.x * 128;
    int tid = threadIdx.x, w = tid >> 5, lane = tid & 31;
    int lr = lane >> 2, lc = lane & 3;

    auto issueK = [&](int j, int buf) {
        #pragma unroll
        for (int i = 0; i < 4; i++) {
            int idx = tid + 256*i;
            int r = idx >> 3, g = idx & 7;
            cp16(Ks + buf*4096 + r*32 + ((g ^ (r & 7)) << 2),
                 &kp[(size_t)(j*128 + r)*LDQ + g*8]);
        }
    };
    auto issueV = [&](int j, int buf) {
        #pragma unroll
        for (int i = 0; i < 4; i++) {
            int idx = tid + 256*i;
            int r = idx >> 4, g = idx & 15;
            cp16(Vs + buf*4096 + r*64 + ((g ^ (r & 7)) << 2),
                 &vt[(size_t)r*Ln + j*128 + g*8]);
        }
    };

    #pragma unroll
    for (int i = 0; i < 4; i++) {
        int idx = tid + 256*i;
        int r = idx >> 3, g = idx & 7;
        cp16(Qs + r*32 + ((g ^ (r & 7)) << 2),
             &q[(size_t)(row0 + r)*LDQ + g*8]);
    }
    issueK(0, 0); issueV(0, 0);
    CP_COMMIT();

    float m0 = -1e30f, m1 = -1e30f, l0 = 0.f, l1 = 0.f;
    float oa[8][4];
    #pragma unroll
    for (int n = 0; n < 8; n++)
        #pragma unroll
        for (int t = 0; t < 4; t++) oa[n][t] = 0.f;

    int arow = w*16 + lr;
    int asw = arow & 7;

    for (int j = 0; j < 8; j++) {
        if (j + 1 < 8) {
            issueK(j + 1, (j + 1) & 1); issueV(j + 1, (j + 1) & 1);
            CP_COMMIT();
            CP_WAIT(1);
        } else {
            CP_WAIT(0);
        }
        __syncthreads();

        const uint32_t* Kb = Ks + (j & 1)*4096;
        const uint32_t* Vb = Vs + (j & 1)*4096;

        // ---- S = Q @ K^T  (k = 64 halfs -> 4 k-steps of 16) ----
        float sacc[16][4];
        #pragma unroll
        for (int n = 0; n < 16; n++)
            #pragma unroll
            for (int t = 0; t < 4; t++) sacc[n][t] = 0.f;

        #pragma unroll
        for (int ks = 0; ks < 4; ks++) {
            const uint32_t* ab  = Qs + arow*32;
            const uint32_t* ab8 = Qs + (arow + 8)*32;
            uint32_t a0 = ab [(((2*ks)   ^ asw) << 2) + lc];
            uint32_t a2 = ab [(((2*ks+1) ^ asw) << 2) + lc];
            uint32_t a1 = ab8[(((2*ks)   ^ asw) << 2) + lc];
            uint32_t a3 = ab8[(((2*ks+1) ^ asw) << 2) + lc];
            #pragma unroll
            for (int nt = 0; nt < 16; nt++) {
                int brow = nt*8 + lr;
                int bsw = brow & 7;
                const uint32_t* bb = Kb + brow*32;
                uint32_t b0 = bb[(((2*ks)   ^ bsw) << 2) + lc];
                uint32_t b1 = bb[(((2*ks+1) ^ bsw) << 2) + lc];
                mma_f16(sacc[nt], a0, a1, a2, a3, b0, b1);
            }
        }

        // ---- online softmax ----
        float rm0 = -1e30f, rm1 = -1e30f;
        #pragma unroll
        for (int nt = 0; nt < 16; nt++) {
            #pragma unroll
            for (int t = 0; t < 4; t++) sacc[nt][t] *= 0.125f;
            rm0 = fmaxf(rm0, fmaxf(sacc[nt][0], sacc[nt][1]));
            rm1 = fmaxf(rm1, fmaxf(sacc[nt][2], sacc[nt][3]));
        }
        rm0 = fmaxf(rm0, __shfl_xor_sync(0xffffffff, rm0, 1));
        rm0 = fmaxf(rm0, __shfl_xor_sync(0xffffffff, rm0, 2));
        rm1 = fmaxf(rm1, __shfl_xor_sync(0xffffffff, rm1, 1));
        rm1 = fmaxf(rm1, __shfl_xor_sync(0xffffffff, rm1, 2));
        float mn0 = fmaxf(m0, rm0), mn1 = fmaxf(m1, rm1);
        float sc0 = expf(m0 - mn0), sc1 = expf(m1 - mn1);

        float rs0 = 0.f, rs1 = 0.f;
        #pragma unroll
        for (int nt = 0; nt < 16; nt++) {
            float p0 = expf(sacc[nt][0] - mn0);
            float p1 = expf(sacc[nt][1] - mn0);
            float p2 = expf(sacc[nt][2] - mn1);
            float p3 = expf(sacc[nt][3] - mn1);
            rs0 += p0 + p1; rs1 += p2 + p3;
            // P store: col pair (nt*8+2lc, +1) -> word nt*4+lc -> group nt, word lc
            *(__half2*)(Ps + arow*64 + ((nt ^ asw) << 2) + lc) = __floats2half2_rn(p0, p1);
            *(__half2*)(Ps + (arow + 8)*64 + ((nt ^ asw) << 2) + lc) = __floats2half2_rn(p2, p3);
        }
        rs0 += __shfl_xor_sync(0xffffffff, rs0, 1);
        rs0 += __shfl_xor_sync(0xffffffff, rs0, 2);
        rs1 += __shfl_xor_sync(0xffffffff, rs1, 1);
        rs1 += __shfl_xor_sync(0xffffffff, rs1, 2);
        l0 = l0*sc0 + rs0; l1 = l1*sc1 + rs1;
        m0 = mn0; m1 = mn1;
        #pragma unroll
        for (int nt = 0; nt < 8; nt++) {
            oa[nt][0] *= sc0; oa[nt][1] *= sc0;
            oa[nt][2] *= sc1; oa[nt][3] *= sc1;
        }
        __syncwarp();

        // ---- O += P @ V^T  (k = 128 halfs -> 8 k-steps of 16) ----
        #pragma unroll
        for (int ks = 0; ks < 8; ks++) {
            const uint32_t* ab  = Ps + arow*64;
            const uint32_t* ab8 = Ps + (arow + 8)*64;
            uint32_t a0 = ab [(((2*ks)   ^ asw) << 2) + lc];
            uint32_t a2 = ab [(((2*ks+1) ^ asw) << 2) + lc];
            uint32_t a1 = ab8[(((2*ks)   ^ asw) << 2) + lc];
            uint32_t a3 = ab8[(((2*ks+1) ^ asw) << 2) + lc];
            #pragma unroll
            for (int nt = 0; nt < 8; nt++) {
                int brow = nt*8 + lr;
                int bsw = brow & 7;
                const uint32_t* bb = Vb + brow*64;
                uint32_t b0 = bb[(((2*ks)   ^ bsw) << 2) + lc];
                uint32_t b1 = bb[(((2*ks+1) ^ bsw) << 2) + lc];
                mma_f16(oa[nt], a0, a1, a2, a3, b0, b1);
            }
        }
        __syncthreads();
    }

    float il0 = 1.f / l0, il1 = 1.f / l1;
    int row = row0 + w*16 + lr;
    #pragma unroll
    for (int nt = 0; nt < 8; nt++) {
        int col = nt*8 + 2*lc;
        *(__half2*)&o[(size_t)row*Dn + col] =
            __floats2half2_rn(oa[nt][0]*il0, oa[nt][1]*il0);
        *(__half2*)&o[(size_t)(row + 8)*Dn + col] =
            __floats2half2_rn(oa[nt][2]*il1, oa[nt][3]*il1);
    }
}

// ======================= transposes =======================
__global__ void k_transpose_f2h(const float* __restrict__ in, int ldin,
                                __half* __restrict__ out, int ldout)
{
    __shared__ float tile[32][33];
    int c0 = blockIdx.x*32, r0 = blockIdx.y*32;
    int tx = threadIdx.x, ty = threadIdx.y;   // 32 x 8
    #pragma unroll
    for (int i = 0; i < 32; i += 8)
        tile[ty+i][tx] = in[(size_t)(r0+ty+i)*ldin + c0+tx];
    __syncthreads();
    #pragma unroll
    for (int i = 0; i < 32; i += 8)
        out[(size_t)(c0+ty+i)*ldout + r0+tx] = __float2half(tile[tx][ty+i]);
}

// half->half transpose with per-z offsets (for V^T): off = z*iS1 + (z>>2)*iS2 + (z&3)*iS3
__global__ void k_transpose_h(const __half* __restrict__ in, int ldin,
                              long iS1, long iS2, long iS3,
                              __half* __restrict__ out, int ldout, long oS1)
{
    __shared__ __half tile[32][34];
    int z = blockIdx.z;
    in  += (long)z*iS1 + (long)(z>>2)*iS2 + (long)(z&3)*iS3;
    out += (long)z*oS1;
    int c0 = blockIdx.x*32, r0 = blockIdx.y*32;
    int tx = threadIdx.x, ty = threadIdx.y;   // 32 x 8
    #pragma unroll
    for (int i = 0; i < 32; i += 8)
        tile[ty+i][tx] = in[(size_t)(r0+ty+i)*ldin + c0+tx];
    __syncthreads();
    #pragma unroll
    for (int i = 0; i < 32; i += 8)
        out[(size_t)(c0+ty+i)*ldout + r0+tx] = tile[tx][ty+i];
}

// ---------------- init / bias concat ----------------
__global__ void k_init(float* compsum, float* kl) {
    int t = threadIdx.x;
    if (t < Bn) compsum[t] = 0.f;
    if (t == 0) kl[0] = 0.f;
}
__global__ void k_bcat(const float* bq, const float* bk, const float* bv, float* o) {
    int t = threadIdx.x;
    o[t] = bq[t]; o[256 + t] = bk[t]; o[512 + t] = bv[t];
}

// ---------------- embedding (half out) ----------------
__global__ void k_embed(const int* __restrict__ sidx, const int* __restrict__ cidx,
                        const float* __restrict__ semb, const float* __restrict__ cemb,
                        __half* __restrict__ x) {
    int tok = blockIdx.x;
    int d = threadIdx.x;
    int si = sidx[tok], ci = cidx[tok];
    x[(size_t)tok*Dn + d] = __float2half(semb[si*Dn + d] + cemb[ci*Dn + d]);
}

// ---------------- LayerNorm (half in; half and/or float out) ----------------
__global__ void k_ln(const __half* __restrict__ T,
                     const float* __restrict__ g, const float* __restrict__ b,
                     __half* __restrict__ Yh, float* __restrict__ Yf) {
    int row = blockIdx.x, d = threadIdx.x;
    __shared__ float red[256];
    float v = __half2float(T[(size_t)row*Dn + d]);
    red[d] = v; __syncthreads();
    for (int o = 128; o > 0; o >>= 1) { if (d < o) red[d] += red[d+o]; __syncthreads(); }
    float m = red[0] * (1.f / Dn); __syncthreads();
    float dv = v - m;
    red[d] = dv * dv; __syncthreads();
    for (int o = 128; o > 0; o >>= 1) { if (d < o) red[d] += red[d+o]; __syncthreads(); }
    float var = red[0] * (1.f / Dn);
    float y = dv * rsqrtf(var + 1e-5f) * g[d] + b[d];
    if (Yh) Yh[(size_t)row*Dn + d] = __float2half(y);
    if (Yf) Yf[(size_t)row*Dn + d] = y;
}

// ---------------- logits + KL + boundary (fp32 y2) ----------------
__global__ void k_logits(const float* __restrict__ Y, const float* __restrict__ Wl,
                         const float* __restrict__ bl, int* __restrict__ closed,
                         float* __restrict__ klacc) {
    int warp = (blockIdx.x * blockDim.x + threadIdx.x) >> 5;
    int lane = threadIdx.x & 31;
    if (warp >= TOK) return;
    const float* y = Y + (size_t)warp * Dn;
    float l0 = 0.f, l1 = 0.f, l2 = 0.f;
    #pragma unroll
    for (int i = 0; i < 8; i++) {
        int d = lane + i * 32;
        float yv = y[d];
        l0 += yv * Wl[d*3 + 0];
        l1 += yv * Wl[d*3 + 1];
        l2 += yv * Wl[d*3 + 2];
    }
    #pragma unroll
    for (int o = 16; o > 0; o >>= 1) {
        l0 += __shfl_xor_sync(0xffffffff, l0, o);
        l1 += __shfl_xor_sync(0xffffffff, l1, o);
        l2 += __shfl_xor_sync(0xffffffff, l2, o);
    }
    if (lane == 0) {
        l0 += bl[0]; l1 += bl[1]; l2 += bl[2];
        float mx = fmaxf(l0, fmaxf(l1, l2));
        float lse = logf(expf(l0-mx) + expf(l1-mx) + expf(l2-mx)) + mx;
        float sumlogp = (l0 + l1 + l2) - 3.f * lse;
        atomicAdd(klacc, sumlogp);
        int l = warp & (Ln - 1);
        int boundary = (l0 >= l1 && l0 >= l2) ? 1 : 0;
        closed[warp] = (boundary && l > 0) ? 1 : 0;
    }
}

// ---------------- per-batch serial segment scan ----------------
__global__ void k_segscan(const int* __restrict__ closed, int* __restrict__ sstart,
                          int* __restrict__ send, int* __restrict__ nseg) {
    int b = threadIdx.x;
    if (b >= Bn) return;
    int cnt = 0, start = 0;
    for (int l = 0; l < Ln; l++) {
        if (closed[b*Ln + l]) {
            sstart[b*Ln + cnt] = start;
            send[b*Ln + cnt] = l;
            cnt++; start = l + 1;
        }
    }
    if (start <= Ln - 1) {
        sstart[b*Ln + cnt] = start;
        send[b*Ln + cnt] = Ln - 1;
        cnt++;
    }
    nseg[b] = cnt;
}

// ---------------- segment mean + predicate net, 8 segments per block ----------------
__global__ void k_segpred8(const float* __restrict__ Y, const float* __restrict__ Wp1,
                           const float* __restrict__ bp1, const float* __restrict__ Wp2,
                           const float* __restrict__ bp2, const float* __restrict__ wc,
                           const float* __restrict__ bc,
                           const int* __restrict__ sstart, const int* __restrict__ send,
                           const int* __restrict__ nseg, float* __restrict__ compsum) {
    int b = blockIdx.y;
    int ns = nseg[b];
    int s0 = blockIdx.x * 8;
    if (s0 >= ns) return;
    int cnt = min(8, ns - s0);
    int d = threadIdx.x;
    __shared__ float mean[8][256];
    for (int s = 0; s < cnt; s++) {
        int st = sstart[b*Ln + s0 + s], en = send[b*Ln + s0 + s];
        float sum = 0.f;
        for (int l = st; l <= en; l++)
            sum += Y[((size_t)(b*Ln + l)) * Dn + d];
        mean[s][d] = sum / (float)(en - st + 1);
    }
    for (int s = cnt; s < 8; s++) mean[s][d] = 0.f;
    __syncthreads();

    float acc[8];
    float bp = bp1[d];
    #pragma unroll
    for (int s = 0; s < 8; s++) acc[s] = bp;
    for (int k = 0; k < Dn; k++) {
        float w = Wp1[k*Dn + d];
        #pragma unroll
        for (int s = 0; s < 8; s++) acc[s] += mean[s][k] * w;
    }

    float w2 = Wp2[d];
    __shared__ float red[256];
    __shared__ float comp_total;
    if (d == 0) comp_total = 0.f;
    __syncthreads();
    for (int s = 0; s < cnt; s++) {
        red[d] = fmaxf(acc[s], 0.f) * w2;
        __syncthreads();
        for (int o = 128; o > 0; o >>= 1) { if (d < o) red[d] += red[d+o]; __syncthreads(); }
        if (d == 0) {
            float pin = red[0] + bp2[0];
            float sig = 1.f / (1.f + expf(-pin));
            comp_total += sig * wc[0] + bc[0];
        }
        __syncthreads();
    }
    if (d == 0) atomicAdd(&compsum[b], comp_total);
}

// ---------------- final outputs ----------------
__global__ void k_final(const float* __restrict__ compsum, const int* __restrict__ nseg,
                        const float* __restrict__ kl, float* __restrict__ out) {
    int t = threadIdx.x;
    if (t < Bn) {
        float mc = compsum[t] / (float)nseg[t];
        out[t] = 1.f / (1.f + expf(-mc));
    }
    if (t == Bn) {
        out[Bn] = ((float)TOK * logf(1.f/3.f) - (1.f/3.f) * kl[0]) / (float)Bn;
    }
}

// =====================================================================
extern "C" void kernel_launch(void* const* d_in, const int* in_sizes, int n_in,
                              void* d_out, int out_size) {
    const int*   sidx = (const int*)d_in[0];
    const int*   cidx = (const int*)d_in[1];
    const float* semb = (const float*)d_in[2];
    const float* cemb = (const float*)d_in[3];
    const float* Wq = (const float*)d_in[4];   const float* bq = (const float*)d_in[5];
    const float* Wk = (const float*)d_in[6];   const float* bk = (const float*)d_in[7];
    const float* Wv = (const float*)d_in[8];   const float* bv = (const float*)d_in[9];
    const float* Wo = (const float*)d_in[10];  const float* bo = (const float*)d_in[11];
    const float* g1 = (const float*)d_in[12];  const float* be1 = (const float*)d_in[13];
    const float* W1 = (const float*)d_in[14];  const float* bf1 = (const float*)d_in[15];
    const float* W2 = (const float*)d_in[16];  const float* bf2 = (const float*)d_in[17];
    const float* g2 = (const float*)d_in[18];  const float* be2 = (const float*)d_in[19];
    const float* Wl = (const float*)d_in[20];  const float* bl = (const float*)d_in[21];
    const float* Wp1 = (const float*)d_in[22]; const float* bp1 = (const float*)d_in[23];
    const float* Wp2 = (const float*)d_in[24]; const float* bp2 = (const float*)d_in[25];
    const float* wc = (const float*)d_in[26];  const float* bc = (const float*)d_in[27];
    float* out = (float*)d_out;

    __half *px, *pqkv, *pvt, *pctx, *pt, *pf, *py1;
    __half *pwqkvT, *pwoT, *pw1T, *pw2T;
    float *py2, *pbqkv, *pcompsum, *pkl;
    int *pclosed, *psegstart, *psegend, *pnseg;
    cudaGetSymbolAddress((void**)&px, g_x);
    cudaGetSymbolAddress((void**)&pqkv, g_qkv);
    cudaGetSymbolAddress((void**)&pvt, g_vt);
    cudaGetSymbolAddress((void**)&pctx, g_ctx);
    cudaGetSymbolAddress((void**)&pt, g_t);
    cudaGetSymbolAddress((void**)&pf, g_f);
    cudaGetSymbolAddress((void**)&py1, g_y1);
    cudaGetSymbolAddress((void**)&py2, g_y2);
    cudaGetSymbolAddress((void**)&pwqkvT, g_wqkvT);
    cudaGetSymbolAddress((void**)&pbqkv, g_bqkv);
    cudaGetSymbolAddress((void**)&pwoT, g_woT);
    cudaGetSymbolAddress((void**)&pw1T, g_w1T);
    cudaGetSymbolAddress((void**)&pw2T, g_w2T);
    cudaGetSymbolAddress((void**)&pclosed, g_closed);
    cudaGetSymbolAddress((void**)&psegstart, g_segstart);
    cudaGetSymbolAddress((void**)&psegend, g_segend);
    cudaGetSymbolAddress((void**)&pnseg, g_nseg);
    cudaGetSymbolAddress((void**)&pcompsum, g_compsum);
    cudaGetSymbolAddress((void**)&pkl, g_kl);

    const int SMEM128 = (3*128*32 + 3*128*32) * 4;   // 98304 B (words)
    const int SMEM64  = (3*128*32 + 3*64*32) * 4;    // 73728
    const int SMEMFL  = (4096 + 8192 + 8192 + 8192) * 4;  // 114688
    cudaFuncSetAttribute(k_mma<128>, cudaFuncAttributeMaxDynamicSharedMemorySize, SMEM128);
    cudaFuncSetAttribute(k_mma<64>,  cudaFuncAttributeMaxDynamicSharedMemorySize, SMEM64);
    cudaFuncSetAttribute(k_flash,    cudaFuncAttributeMaxDynamicSharedMemorySize, SMEMFL);

    k_init<<<1, 32>>>(pcompsum, pkl);
    k_bcat<<<1, 256>>>(bq, bk, bv, pbqkv);
    k_embed<<<TOK, Dn>>>(sidx, cidx, semb, cemb, px);

    dim3 tb(32, 8);
    k_transpose_f2h<<<dim3(Dn/32, Dn/32), tb>>>(Wq, Dn, pwqkvT, Dn);
    k_transpose_f2h<<<dim3(Dn/32, Dn/32), tb>>>(Wk, Dn, pwqkvT + Dn*Dn, Dn);
    k_transpose_f2h<<<dim3(Dn/32, Dn/32), tb>>>(Wv, Dn, pwqkvT + 2*Dn*Dn, Dn);
    k_transpose_f2h<<<dim3(Dn/32, Dn/32), tb>>>(Wo, Dn, pwoT, Dn);
    k_transpose_f2h<<<dim3(DFFn/32, Dn/32), tb>>>(W1, DFFn, pw1T, Dn);
    k_transpose_f2h<<<dim3(Dn/32, DFFn/32), tb>>>(W2, Dn, pw2T, DFFn);

    // merged QKV projection: [16384,768] = x @ Wqkv
    k_mma<128><<<dim3(6, TOK/128, 1), 256, SMEM128>>>(px, Dn, pwqkvT, Dn,
                                                      pqkv, LDQ, Dn, pbqkv, 0, 1.f, nullptr);

    // V^T per (b,h): [64][1024] from qkv v-section
    k_transpose_h<<<dim3(DHn/32, Ln/32, Bn*Hn), tb>>>(pqkv + 512, LDQ, 0, (long)Ln*LDQ, DHn,
                                                      pvt, Ln, (long)DHn*Ln);

    // fused flash attention
    k_flash<<<dim3(Ln/128, Bn*Hn), 256, SMEMFL>>>(pqkv, pvt, pctx);

    // attn out proj + residual(x), then LN1 (half out)
    k_mma<64><<<dim3(4, TOK/128, 1), 256, SMEM64>>>(pctx, Dn, pwoT, Dn,
                                                    pt, Dn, Dn, bo, 0, 1.f, px);
    k_ln<<<TOK, Dn>>>(pt, g1, be1, py1, nullptr);

    // FFN (FFN2 fuses residual py1); LN2 writes fp32 y2
    k_mma<128><<<dim3(16, TOK/128, 1), 256, SMEM128>>>(py1, Dn, pw1T, Dn,
                                                       pt, DFFn, Dn, bf1, 1, 1.f, nullptr);
    k_mma<64><<<dim3(4, TOK/128, 1), 256, SMEM64>>>(pt, DFFn, pw2T, DFFn,
                                                    pf, Dn, DFFn, bf2, 0, 1.f, py1);
    k_ln<<<TOK, Dn>>>(pf, g2, be2, nullptr, py2);

    // logits / KL / boundaries / segments (fp32 path)
    k_logits<<<TOK/8, 256>>>(py2, Wl, bl, pclosed, pkl);
    k_segscan<<<1, Bn>>>(pclosed, psegstart, psegend, pnseg);

    dim3 gSeg(Ln/8, Bn, 1);
    k_segpred8<<<gSeg, 256>>>(py2, Wp1, bp1, Wp2, bp2, wc, bc,
                              psegstart, psegend, pnseg, pcompsum);

    k_final<<<1, 32>>>(pcompsum, pnseg, pkl, out);

    (void)in_sizes; (void)n_in; (void)out_size;
}